// round 4
// baseline (speedup 1.0000x reference)
#include <cuda_runtime.h>
#include <math.h>

// Problem dims
#define BB 2
#define DD 128
#define HH 128
#define WW 128
#define CW 0.1f
#define TWO_PI 6.283185307179586f

typedef unsigned long long u64;

// ---------------------------------------------------------------------------
// f32x2 packed-FMA helpers (sm_100+): one issue slot, two FMAs.
// ---------------------------------------------------------------------------
__device__ __forceinline__ void ffma2(u64& d, u64 a, u64 b) {
    asm("fma.rn.f32x2 %0, %1, %2, %0;" : "+l"(d) : "l"(a), "l"(b));
}
__device__ __forceinline__ u64 pack2f(float lo, float hi) {
    u64 r; asm("mov.b64 %0, {%1, %2};" : "=l"(r) : "f"(lo), "f"(hi)); return r;
}
__device__ __forceinline__ void unpack2f(u64 v, float& lo, float& hi) {
    asm("mov.b64 {%0, %1}, %2;" : "=f"(lo), "=f"(hi) : "l"(v));
}

// Channels-last scratch buffers (__device__ globals, not cudaMalloc)
__device__ float g_s1[(size_t)BB * DD * HH * WW * 8];    // conv1 out, [b][d][h][w][8]
__device__ float g_s2[(size_t)BB * DD * HH * WW * 16];   // conv2 out, [b][d][h][w][16]

// ---------------------------------------------------------------------------
// Kernel 1: field modulation + conv3d(1->8) + ReLU
// co-paired f32x2; low register pressure (4 u64 accs) -- measured neutral.
// ---------------------------------------------------------------------------
__global__ __launch_bounds__(512, 2)
void k_conv1(const float* __restrict__ x,
             const float* __restrict__ w1,
             const float* __restrict__ b1)
{
    __shared__ __align__(16) float tile[10 * 10 * 10];
    __shared__ __align__(16) float wk[27 * 8];
    __shared__ float bs[8];

    const int tx = threadIdx.x, ty = threadIdx.y, tz = threadIdx.z;
    const int tid = (tz * 8 + ty) * 8 + tx;
    const int b  = blockIdx.z >> 4;
    const int z0 = (blockIdx.z & 15) << 3;
    const int y0 = blockIdx.y << 3;
    const int x0 = blockIdx.x << 3;

    if (tid < 216) {
        int tap = tid >> 3, co = tid & 7;
        wk[tid] = w1[co * 27 + tap];
    }
    if (tid < 8) bs[tid] = b1[tid];

    const float inv = TWO_PI / (float)(DD + HH + WW);
    for (int idx = tid; idx < 1000; idx += 512) {
        int lz = idx / 100, r = idx % 100, ly = r / 10, lx = r % 10;
        int gz = z0 - 1 + lz, gy = y0 - 1 + ly, gx = x0 - 1 + lx;
        float v = 0.0f;
        if (gz >= 0 && gz < DD && gy >= 0 && gy < HH && gx >= 0 && gx < WW) {
            v = x[(((size_t)b * DD + gz) * HH + gy) * WW + gx];
            float s = (float)(gz + gy + gx);
            v *= 1.0f + CW * sinf(inv * s);
        }
        tile[idx] = v;
    }
    __syncthreads();

    u64 acc2[4];
#pragma unroll
    for (int q = 0; q < 4; q++) acc2[q] = pack2f(bs[2 * q], bs[2 * q + 1]);

#pragma unroll
    for (int kz = 0; kz < 3; kz++)
#pragma unroll
        for (int ky = 0; ky < 3; ky++)
#pragma unroll
            for (int kx = 0; kx < 3; kx++) {
                float v = tile[((tz + kz) * 10 + (ty + ky)) * 10 + (tx + kx)];
                u64 vv = pack2f(v, v);
                const int tap = (kz * 3 + ky) * 3 + kx;
                ulonglong2 w0 = *(const ulonglong2*)&wk[tap * 8];
                ulonglong2 w1v = *(const ulonglong2*)&wk[tap * 8 + 4];
                ffma2(acc2[0], vv, w0.x);
                ffma2(acc2[1], vv, w0.y);
                ffma2(acc2[2], vv, w1v.x);
                ffma2(acc2[3], vv, w1v.y);
            }

    const int gz = z0 + tz, gy = y0 + ty, gx = x0 + tx;
    size_t out = ((((size_t)b * DD + gz) * HH + gy) * WW + gx) * 8;
    float r[8];
#pragma unroll
    for (int q = 0; q < 4; q++) {
        float lo, hi; unpack2f(acc2[q], lo, hi);
        r[2 * q]     = fmaxf(lo, 0.0f);
        r[2 * q + 1] = fmaxf(hi, 0.0f);
    }
    *(float4*)&g_s1[out]     = make_float4(r[0], r[1], r[2], r[3]);
    *(float4*)&g_s1[out + 4] = make_float4(r[4], r[5], r[6], r[7]);
}

// ---------------------------------------------------------------------------
// Kernel 2: conv3d(8->16) + ReLU  -- FFMA2-bound core
// ci-paired f32x2; FOUR passes of 4 output channels each, so the live
// register-pair set per pass is only ~12 pairs (4 acc + 4 input + 4 weight)
// -> no spills under the 64-reg cap (the R2 regression cause).
// Weights pre-interleaved in smem: ws2[(tap*4+p)*16+co] = (w[2p][co], w[2p+1][co]).
// ---------------------------------------------------------------------------
__global__ __launch_bounds__(512, 2)
void k_conv2(const float* __restrict__ w2,
             const float* __restrict__ b2)
{
    __shared__ __align__(16) float tile[1000 * 8];     // 32 KB, AoS [pos][ci]
    __shared__ __align__(16) float2 ws2[27 * 4 * 16];  // 13.8 KB
    __shared__ float bs[16];

    const int tx = threadIdx.x, ty = threadIdx.y, tz = threadIdx.z;
    const int tid = (tz * 8 + ty) * 8 + tx;
    const int b  = blockIdx.z >> 4;
    const int z0 = (blockIdx.z & 15) << 3;
    const int y0 = blockIdx.y << 3;
    const int x0 = blockIdx.x << 3;

    for (int i = tid; i < 1728; i += 512) {
        int tap = i >> 6, rr = i & 63, p = rr >> 4, co = rr & 15;
        ws2[i] = make_float2(w2[(co * 8 + 2 * p)     * 27 + tap],
                             w2[(co * 8 + 2 * p + 1) * 27 + tap]);
    }
    if (tid < 16) bs[tid] = b2[tid];

    for (int idx = tid; idx < 1000; idx += 512) {
        int lz = idx / 100, rr = idx % 100, ly = rr / 10, lx = rr % 10;
        int gz = z0 - 1 + lz, gy = y0 - 1 + ly, gx = x0 - 1 + lx;
        float4 a = make_float4(0.f, 0.f, 0.f, 0.f), c = a;
        if (gz >= 0 && gz < DD && gy >= 0 && gy < HH && gx >= 0 && gx < WW) {
            size_t base = ((((size_t)b * DD + gz) * HH + gy) * WW + gx) * 8;
            a = *(const float4*)&g_s1[base];
            c = *(const float4*)&g_s1[base + 4];
        }
        *(float4*)&tile[idx * 8]     = a;
        *(float4*)&tile[idx * 8 + 4] = c;
    }
    __syncthreads();

    const int gz = z0 + tz, gy = y0 + ty, gx = x0 + tx;
    const size_t voxout = ((((size_t)b * DD + gz) * HH + gy) * WW + gx) * 16;
    const int tilebase = ((tz * 10 + ty) * 10 + tx) * 8;  // (kz,ky,kx)=(0,0,0) corner

#pragma unroll
    for (int pass = 0; pass < 4; pass++) {
        const int coBase = pass * 4;
        u64 acc2[4];
#pragma unroll
        for (int q = 0; q < 4; q++) acc2[q] = pack2f(bs[coBase + q], 0.0f);

#pragma unroll
        for (int kz = 0; kz < 3; kz++)
#pragma unroll
            for (int ky = 0; ky < 3; ky++)
#pragma unroll
                for (int kx = 0; kx < 3; kx++) {
                    const int tap = (kz * 3 + ky) * 3 + kx;
                    const float* ip = &tile[tilebase + ((kz * 10 + ky) * 10 + kx) * 8];
                    ulonglong2 iv0 = *(const ulonglong2*)ip;        // (ci0,ci1),(ci2,ci3)
                    ulonglong2 iv1 = *(const ulonglong2*)(ip + 4);  // (ci4,ci5),(ci6,ci7)
#pragma unroll
                    for (int p = 0; p < 4; p++) {
                        const u64 a = (p == 0) ? iv0.x : (p == 1) ? iv0.y
                                    : (p == 2) ? iv1.x : iv1.y;
                        // 4 co-pairs for this (tap,p): 2 x LDS.128 (broadcast)
                        ulonglong2 wA =
                            *(const ulonglong2*)&ws2[(tap * 4 + p) * 16 + coBase];
                        ffma2(acc2[0], a, wA.x);
                        ffma2(acc2[1], a, wA.y);
                        ulonglong2 wB =
                            *(const ulonglong2*)&ws2[(tap * 4 + p) * 16 + coBase + 2];
                        ffma2(acc2[2], a, wB.x);
                        ffma2(acc2[3], a, wB.y);
                    }
                }

        float r[4];
#pragma unroll
        for (int q = 0; q < 4; q++) {
            float lo, hi; unpack2f(acc2[q], lo, hi);
            r[q] = fmaxf(lo + hi, 0.0f);
        }
        *(float4*)&g_s2[voxout + coBase * 1] = make_float4(r[0], r[1], r[2], r[3]);
    }
}

// ---------------------------------------------------------------------------
// Kernel 3: conv3d(16->1) + tanh -- ci-paired f32x2, low pressure (4 pairs)
// ---------------------------------------------------------------------------
extern __shared__ __align__(16) float dyn_tile[];

__global__ __launch_bounds__(512, 2)
void k_conv3(const float* __restrict__ w3,
             const float* __restrict__ b3,
             float* __restrict__ out)
{
    __shared__ __align__(16) float ws[27 * 16];
    __shared__ float bsv;

    const int tx = threadIdx.x, ty = threadIdx.y, tz = threadIdx.z;
    const int tid = (tz * 8 + ty) * 8 + tx;
    const int b  = blockIdx.z >> 4;
    const int z0 = (blockIdx.z & 15) << 3;
    const int y0 = blockIdx.y << 3;
    const int x0 = blockIdx.x << 3;

    if (tid < 432) {
        int tap = tid >> 4, ci = tid & 15;
        ws[tid] = w3[ci * 27 + tap];
    }
    if (tid == 0) bsv = b3[0];

    for (int idx = tid; idx < 4000; idx += 512) {
        int pos = idx >> 2, q = idx & 3;
        int lz = pos / 100, rr = pos % 100, ly = rr / 10, lx = rr % 10;
        int gz = z0 - 1 + lz, gy = y0 - 1 + ly, gx = x0 - 1 + lx;
        float4 v = make_float4(0.f, 0.f, 0.f, 0.f);
        if (gz >= 0 && gz < DD && gy >= 0 && gy < HH && gx >= 0 && gx < WW) {
            size_t base = ((((size_t)b * DD + gz) * HH + gy) * WW + gx) * 16;
            v = *(const float4*)&g_s2[base + q * 4];
        }
        *(float4*)&dyn_tile[pos * 16 + q * 4] = v;
    }
    __syncthreads();

    u64 acc2[4];
    acc2[0] = pack2f(bsv, 0.0f);
    acc2[1] = pack2f(0.0f, 0.0f);
    acc2[2] = pack2f(0.0f, 0.0f);
    acc2[3] = pack2f(0.0f, 0.0f);

#pragma unroll
    for (int kz = 0; kz < 3; kz++)
#pragma unroll
        for (int ky = 0; ky < 3; ky++)
#pragma unroll
            for (int kx = 0; kx < 3; kx++) {
                const int tap = (kz * 3 + ky) * 3 + kx;
                const float* ip =
                    &dyn_tile[(((tz + kz) * 10 + (ty + ky)) * 10 + (tx + kx)) * 16];
                const ulonglong2* ia = (const ulonglong2*)ip;
                const ulonglong2* wa = (const ulonglong2*)&ws[tap * 16];
                ulonglong2 i0 = ia[0];
                ulonglong2 w0 = wa[0];
                ffma2(acc2[0], i0.x, w0.x);
                ffma2(acc2[1], i0.y, w0.y);
                ulonglong2 i1 = ia[1];
                ulonglong2 w1 = wa[1];
                ffma2(acc2[2], i1.x, w1.x);
                ffma2(acc2[3], i1.y, w1.y);
                ulonglong2 i2 = ia[2];
                ulonglong2 w2v = wa[2];
                ffma2(acc2[0], i2.x, w2v.x);
                ffma2(acc2[1], i2.y, w2v.y);
                ulonglong2 i3 = ia[3];
                ulonglong2 w3v = wa[3];
                ffma2(acc2[2], i3.x, w3v.x);
                ffma2(acc2[3], i3.y, w3v.y);
            }

    float tot = 0.0f;
#pragma unroll
    for (int q = 0; q < 4; q++) {
        float lo, hi; unpack2f(acc2[q], lo, hi);
        tot += lo + hi;
    }

    const int gz = z0 + tz, gy = y0 + ty, gx = x0 + tx;
    out[(((size_t)b * DD + gz) * HH + gy) * WW + gx] = tanhf(tot);
}

// ---------------------------------------------------------------------------
extern "C" void kernel_launch(void* const* d_in, const int* in_sizes, int n_in,
                              void* d_out, int out_size)
{
    const float* x  = (const float*)d_in[0];
    const float* w1 = (const float*)d_in[1];
    const float* b1 = (const float*)d_in[2];
    const float* w2 = (const float*)d_in[3];
    const float* b2 = (const float*)d_in[4];
    const float* w3 = (const float*)d_in[5];
    const float* b3 = (const float*)d_in[6];
    float* out = (float*)d_out;

    static bool attr_set = false;  // idempotent attribute set (not a work guard)
    if (!attr_set) {
        cudaFuncSetAttribute(k_conv3, cudaFuncAttributeMaxDynamicSharedMemorySize,
                             10 * 10 * 10 * 16 * sizeof(float));
        attr_set = true;
    }

    dim3 blk(8, 8, 8);
    dim3 grd(WW / 8, HH / 8, (DD / 8) * BB);

    k_conv1<<<grd, blk>>>(x, w1, b1);
    k_conv2<<<grd, blk>>>(w2, b2);
    k_conv3<<<grd, blk, 10 * 10 * 10 * 16 * sizeof(float)>>>(w3, b3, out);
}

// round 5
// speedup vs baseline: 4.1918x; 4.1918x over previous
#include <cuda_runtime.h>
#include <math.h>

// Problem dims
#define BB 2
#define DD 128
#define HH 128
#define WW 128
#define CW 0.1f
#define TWO_PI 6.283185307179586f

// Channels-last scratch buffers (__device__ globals, not cudaMalloc)
__device__ float g_s1[(size_t)BB * DD * HH * WW * 8];    // conv1 out, [b][d][h][w][8]
__device__ float g_s2[(size_t)BB * DD * HH * WW * 16];   // conv2 out, [b][d][h][w][16]

// ---------------------------------------------------------------------------
// Kernel 1: field modulation + conv3d(1->8) + ReLU  (R1 scalar form, 128us)
// ---------------------------------------------------------------------------
__global__ __launch_bounds__(512, 2)
void k_conv1(const float* __restrict__ x,
             const float* __restrict__ w1,
             const float* __restrict__ b1)
{
    __shared__ __align__(16) float tile[10 * 10 * 10];
    __shared__ __align__(16) float wk[27 * 8];   // [tap][co]
    __shared__ float bs[8];

    const int tx = threadIdx.x, ty = threadIdx.y, tz = threadIdx.z;
    const int tid = (tz * 8 + ty) * 8 + tx;
    const int b  = blockIdx.z >> 4;
    const int z0 = (blockIdx.z & 15) << 3;
    const int y0 = blockIdx.y << 3;
    const int x0 = blockIdx.x << 3;

    if (tid < 216) {
        int tap = tid >> 3, co = tid & 7;
        wk[tid] = w1[co * 27 + tap];
    }
    if (tid < 8) bs[tid] = b1[tid];

    const float inv = TWO_PI / (float)(DD + HH + WW);
    for (int idx = tid; idx < 1000; idx += 512) {
        int lz = idx / 100, r = idx % 100, ly = r / 10, lx = r % 10;
        int gz = z0 - 1 + lz, gy = y0 - 1 + ly, gx = x0 - 1 + lx;
        float v = 0.0f;
        if (gz >= 0 && gz < DD && gy >= 0 && gy < HH && gx >= 0 && gx < WW) {
            v = x[(((size_t)b * DD + gz) * HH + gy) * WW + gx];
            float s = (float)(gz + gy + gx);
            v *= 1.0f + CW * sinf(inv * s);
        }
        tile[idx] = v;
    }
    __syncthreads();

    float acc[8];
#pragma unroll
    for (int c = 0; c < 8; c++) acc[c] = bs[c];

#pragma unroll
    for (int kz = 0; kz < 3; kz++)
#pragma unroll
        for (int ky = 0; ky < 3; ky++)
#pragma unroll
            for (int kx = 0; kx < 3; kx++) {
                float v = tile[((tz + kz) * 10 + (ty + ky)) * 10 + (tx + kx)];
                int tap = (kz * 3 + ky) * 3 + kx;
                float4 wa = *(const float4*)&wk[tap * 8];
                float4 wb = *(const float4*)&wk[tap * 8 + 4];
                acc[0] = fmaf(v, wa.x, acc[0]);
                acc[1] = fmaf(v, wa.y, acc[1]);
                acc[2] = fmaf(v, wa.z, acc[2]);
                acc[3] = fmaf(v, wa.w, acc[3]);
                acc[4] = fmaf(v, wb.x, acc[4]);
                acc[5] = fmaf(v, wb.y, acc[5]);
                acc[6] = fmaf(v, wb.z, acc[6]);
                acc[7] = fmaf(v, wb.w, acc[7]);
            }

    const int gz = z0 + tz, gy = y0 + ty, gx = x0 + tx;
    size_t out = ((((size_t)b * DD + gz) * HH + gy) * WW + gx) * 8;
#pragma unroll
    for (int c = 0; c < 8; c++) acc[c] = fmaxf(acc[c], 0.0f);
    *(float4*)&g_s1[out]     = make_float4(acc[0], acc[1], acc[2], acc[3]);
    *(float4*)&g_s1[out + 4] = make_float4(acc[4], acc[5], acc[6], acc[7]);
}

// ---------------------------------------------------------------------------
// Kernel 2: conv3d(8->16) + ReLU -- register-tiled scalar version.
// Block (4,8,8)=256 threads, output tile 16x8x8; each thread computes a
// 4-voxel x-strip and ALL 16 output channels (acc[4][16]).
// Per (kz,ky): the 6-position input window is cached in registers and the
// weights are loaded once per (kx,ci) and reused across 4 voxels ->
// FFMA dominates LDS wavefronts ~4x (R1 was LDS-co-bound).
// __launch_bounds__(256,1): 255-reg budget, guaranteed no spills.
// ---------------------------------------------------------------------------
__global__ __launch_bounds__(256, 1)
void k_conv2(const float* __restrict__ w2,
             const float* __restrict__ b2)
{
    extern __shared__ __align__(16) float dsm[];   // 10*10*18*8 = 14400 floats (57.6 KB)
    __shared__ __align__(16) float ws[27 * 128];   // [tap][ci][co16], 13.8 KB
    __shared__ float bs[16];

    const int tx4 = threadIdx.x;           // 0..3 (x-strip group)
    const int ty  = threadIdx.y;           // 0..7
    const int tz  = threadIdx.z;           // 0..7
    const int tid = (tz * 8 + ty) * 4 + tx4;
    const int b  = blockIdx.z >> 4;
    const int z0 = (blockIdx.z & 15) << 3;
    const int y0 = blockIdx.y << 3;
    const int x0 = blockIdx.x << 4;        // 16-wide x tile

    // ws[tap*128 + ci*16 + co] = w2[(co*8+ci)*27 + tap]
    for (int i = tid; i < 3456; i += 256) {
        int tap = i >> 7, r = i & 127, ci = r >> 4, co = r & 15;
        ws[i] = w2[(co * 8 + ci) * 27 + tap];
    }
    if (tid < 16) bs[tid] = b2[tid];

    // stage input tile [lz 0..9][ly 0..9][lx 0..17][ci 0..7]
    for (int idx = tid; idx < 1800; idx += 256) {
        int lz = idx / 180, r = idx % 180, ly = r / 18, lx = r % 18;
        int gz = z0 - 1 + lz, gy = y0 - 1 + ly, gx = x0 - 1 + lx;
        float4 a = make_float4(0.f, 0.f, 0.f, 0.f), c = a;
        if (gz >= 0 && gz < DD && gy >= 0 && gy < HH && gx >= 0 && gx < WW) {
            size_t base = ((((size_t)b * DD + gz) * HH + gy) * WW + gx) * 8;
            a = *(const float4*)&g_s1[base];
            c = *(const float4*)&g_s1[base + 4];
        }
        *(float4*)&dsm[idx * 8]     = a;
        *(float4*)&dsm[idx * 8 + 4] = c;
    }
    __syncthreads();

    float acc[4][16];
#pragma unroll
    for (int v = 0; v < 4; v++)
#pragma unroll
        for (int co = 0; co < 16; co++) acc[v][co] = bs[co];

    const int xb = tx4 * 4;

    for (int kz = 0; kz < 3; kz++)
        for (int ky = 0; ky < 3; ky++) {
            const float* rb = &dsm[(((tz + kz) * 10 + (ty + ky)) * 18 + xb) * 8];
            float in_r[6][8];
#pragma unroll
            for (int p = 0; p < 6; p++) {
                *(float4*)&in_r[p][0] = *(const float4*)(rb + p * 8);
                *(float4*)&in_r[p][4] = *(const float4*)(rb + p * 8 + 4);
            }
            const float* wrow = &ws[(kz * 3 + ky) * 3 * 128];
#pragma unroll
            for (int kx = 0; kx < 3; kx++) {
                const float* wb = wrow + kx * 128;
#pragma unroll
                for (int ci = 0; ci < 8; ci++) {
                    float4 wa = *(const float4*)&wb[ci * 16];
                    float4 wc = *(const float4*)&wb[ci * 16 + 4];
                    float4 we = *(const float4*)&wb[ci * 16 + 8];
                    float4 wg = *(const float4*)&wb[ci * 16 + 12];
#pragma unroll
                    for (int v = 0; v < 4; v++) {
                        float iv = in_r[kx + v][ci];
                        acc[v][0]  = fmaf(iv, wa.x, acc[v][0]);
                        acc[v][1]  = fmaf(iv, wa.y, acc[v][1]);
                        acc[v][2]  = fmaf(iv, wa.z, acc[v][2]);
                        acc[v][3]  = fmaf(iv, wa.w, acc[v][3]);
                        acc[v][4]  = fmaf(iv, wc.x, acc[v][4]);
                        acc[v][5]  = fmaf(iv, wc.y, acc[v][5]);
                        acc[v][6]  = fmaf(iv, wc.z, acc[v][6]);
                        acc[v][7]  = fmaf(iv, wc.w, acc[v][7]);
                        acc[v][8]  = fmaf(iv, we.x, acc[v][8]);
                        acc[v][9]  = fmaf(iv, we.y, acc[v][9]);
                        acc[v][10] = fmaf(iv, we.z, acc[v][10]);
                        acc[v][11] = fmaf(iv, we.w, acc[v][11]);
                        acc[v][12] = fmaf(iv, wg.x, acc[v][12]);
                        acc[v][13] = fmaf(iv, wg.y, acc[v][13]);
                        acc[v][14] = fmaf(iv, wg.z, acc[v][14]);
                        acc[v][15] = fmaf(iv, wg.w, acc[v][15]);
                    }
                }
            }
        }

    const int gz = z0 + tz, gy = y0 + ty;
#pragma unroll
    for (int v = 0; v < 4; v++) {
        const int gx = x0 + xb + v;
        size_t outb = ((((size_t)b * DD + gz) * HH + gy) * WW + gx) * 16;
#pragma unroll
        for (int q = 0; q < 4; q++) {
            float r0 = fmaxf(acc[v][q * 4 + 0], 0.0f);
            float r1 = fmaxf(acc[v][q * 4 + 1], 0.0f);
            float r2 = fmaxf(acc[v][q * 4 + 2], 0.0f);
            float r3 = fmaxf(acc[v][q * 4 + 3], 0.0f);
            *(float4*)&g_s2[outb + q * 4] = make_float4(r0, r1, r2, r3);
        }
    }
}

// ---------------------------------------------------------------------------
// Kernel 3: conv3d(16->1) + tanh  (R1 scalar form)
// ---------------------------------------------------------------------------
extern __shared__ __align__(16) float dyn_tile[];

__global__ __launch_bounds__(512, 2)
void k_conv3(const float* __restrict__ w3,
             const float* __restrict__ b3,
             float* __restrict__ out)
{
    __shared__ __align__(16) float ws[27 * 16];  // [tap][ci]
    __shared__ float bsv;

    const int tx = threadIdx.x, ty = threadIdx.y, tz = threadIdx.z;
    const int tid = (tz * 8 + ty) * 8 + tx;
    const int b  = blockIdx.z >> 4;
    const int z0 = (blockIdx.z & 15) << 3;
    const int y0 = blockIdx.y << 3;
    const int x0 = blockIdx.x << 3;

    if (tid < 432) {
        int tap = tid >> 4, ci = tid & 15;
        ws[tid] = w3[ci * 27 + tap];
    }
    if (tid == 0) bsv = b3[0];

    for (int idx = tid; idx < 4000; idx += 512) {
        int pos = idx >> 2, q = idx & 3;
        int lz = pos / 100, rr = pos % 100, ly = rr / 10, lx = rr % 10;
        int gz = z0 - 1 + lz, gy = y0 - 1 + ly, gx = x0 - 1 + lx;
        float4 v = make_float4(0.f, 0.f, 0.f, 0.f);
        if (gz >= 0 && gz < DD && gy >= 0 && gy < HH && gx >= 0 && gx < WW) {
            size_t base = ((((size_t)b * DD + gz) * HH + gy) * WW + gx) * 16;
            v = *(const float4*)&g_s2[base + q * 4];
        }
        *(float4*)&dyn_tile[pos * 16 + q * 4] = v;
    }
    __syncthreads();

    float acc = bsv;
#pragma unroll
    for (int kz = 0; kz < 3; kz++)
#pragma unroll
        for (int ky = 0; ky < 3; ky++)
#pragma unroll
            for (int kx = 0; kx < 3; kx++) {
                const int tap = (kz * 3 + ky) * 3 + kx;
                const float* ip =
                    &dyn_tile[(((tz + kz) * 10 + (ty + ky)) * 10 + (tx + kx)) * 16];
                const float* wb = &ws[tap * 16];
#pragma unroll
                for (int q = 0; q < 4; q++) {
                    float4 iv = *(const float4*)&ip[q * 4];
                    float4 wv = *(const float4*)&wb[q * 4];
                    acc = fmaf(iv.x, wv.x, acc);
                    acc = fmaf(iv.y, wv.y, acc);
                    acc = fmaf(iv.z, wv.z, acc);
                    acc = fmaf(iv.w, wv.w, acc);
                }
            }

    const int gz = z0 + tz, gy = y0 + ty, gx = x0 + tx;
    out[(((size_t)b * DD + gz) * HH + gy) * WW + gx] = tanhf(acc);
}

// ---------------------------------------------------------------------------
extern "C" void kernel_launch(void* const* d_in, const int* in_sizes, int n_in,
                              void* d_out, int out_size)
{
    const float* x  = (const float*)d_in[0];
    const float* w1 = (const float*)d_in[1];
    const float* b1 = (const float*)d_in[2];
    const float* w2 = (const float*)d_in[3];
    const float* b2 = (const float*)d_in[4];
    const float* w3 = (const float*)d_in[5];
    const float* b3 = (const float*)d_in[6];
    float* out = (float*)d_out;

    static bool attr_set = false;  // idempotent attribute set (not a work guard)
    if (!attr_set) {
        cudaFuncSetAttribute(k_conv2, cudaFuncAttributeMaxDynamicSharedMemorySize,
                             10 * 10 * 18 * 8 * sizeof(float));
        cudaFuncSetAttribute(k_conv3, cudaFuncAttributeMaxDynamicSharedMemorySize,
                             10 * 10 * 10 * 16 * sizeof(float));
        attr_set = true;
    }

    dim3 blk1(8, 8, 8);
    dim3 grd1(WW / 8, HH / 8, (DD / 8) * BB);
    dim3 blk2(4, 8, 8);
    dim3 grd2(WW / 16, HH / 8, (DD / 8) * BB);

    k_conv1<<<grd1, blk1>>>(x, w1, b1);
    k_conv2<<<grd2, blk2, 10 * 10 * 18 * 8 * sizeof(float)>>>(w2, b2);
    k_conv3<<<grd1, blk1, 10 * 10 * 10 * 16 * sizeof(float)>>>(w3, b3, out);
}

// round 7
// speedup vs baseline: 6.5377x; 1.5596x over previous
#include <cuda_runtime.h>
#include <cuda_fp16.h>
#include <math.h>

// Problem dims
#define BB 2
#define DD 128
#define HH 128
#define WW 128
#define CW 0.1f
#define TWO_PI 6.283185307179586f

// Channels-last scratch buffers (__device__ globals, not cudaMalloc)
__device__ float  g_s1[(size_t)BB * DD * HH * WW * 8];    // conv1 out fp32, [b][d][h][w][8]
__device__ __half g_s2h[(size_t)BB * DD * HH * WW * 16];  // conv2 out fp16, [b][d][h][w][16]

// ---------------------------------------------------------------------------
// Kernel 1: field modulation + conv3d(1->8) + ReLU  (proven form, ~128us)
// ---------------------------------------------------------------------------
__global__ __launch_bounds__(512, 2)
void k_conv1(const float* __restrict__ x,
             const float* __restrict__ w1,
             const float* __restrict__ b1)
{
    __shared__ __align__(16) float tile[10 * 10 * 10];
    __shared__ __align__(16) float wk[27 * 8];   // [tap][co]
    __shared__ float bs[8];

    const int tx = threadIdx.x, ty = threadIdx.y, tz = threadIdx.z;
    const int tid = (tz * 8 + ty) * 8 + tx;
    const int b  = blockIdx.z >> 4;
    const int z0 = (blockIdx.z & 15) << 3;
    const int y0 = blockIdx.y << 3;
    const int x0 = blockIdx.x << 3;

    if (tid < 216) {
        int tap = tid >> 3, co = tid & 7;
        wk[tid] = w1[co * 27 + tap];
    }
    if (tid < 8) bs[tid] = b1[tid];

    const float inv = TWO_PI / (float)(DD + HH + WW);
    for (int idx = tid; idx < 1000; idx += 512) {
        int lz = idx / 100, r = idx % 100, ly = r / 10, lx = r % 10;
        int gz = z0 - 1 + lz, gy = y0 - 1 + ly, gx = x0 - 1 + lx;
        float v = 0.0f;
        if (gz >= 0 && gz < DD && gy >= 0 && gy < HH && gx >= 0 && gx < WW) {
            v = x[(((size_t)b * DD + gz) * HH + gy) * WW + gx];
            float s = (float)(gz + gy + gx);
            v *= 1.0f + CW * sinf(inv * s);
        }
        tile[idx] = v;
    }
    __syncthreads();

    float acc[8];
#pragma unroll
    for (int c = 0; c < 8; c++) acc[c] = bs[c];

#pragma unroll
    for (int kz = 0; kz < 3; kz++)
#pragma unroll
        for (int ky = 0; ky < 3; ky++)
#pragma unroll
            for (int kx = 0; kx < 3; kx++) {
                float v = tile[((tz + kz) * 10 + (ty + ky)) * 10 + (tx + kx)];
                int tap = (kz * 3 + ky) * 3 + kx;
                float4 wa = *(const float4*)&wk[tap * 8];
                float4 wb = *(const float4*)&wk[tap * 8 + 4];
                acc[0] = fmaf(v, wa.x, acc[0]);
                acc[1] = fmaf(v, wa.y, acc[1]);
                acc[2] = fmaf(v, wa.z, acc[2]);
                acc[3] = fmaf(v, wa.w, acc[3]);
                acc[4] = fmaf(v, wb.x, acc[4]);
                acc[5] = fmaf(v, wb.y, acc[5]);
                acc[6] = fmaf(v, wb.z, acc[6]);
                acc[7] = fmaf(v, wb.w, acc[7]);
            }

    const int gz = z0 + tz, gy = y0 + ty, gx = x0 + tx;
    size_t out = ((((size_t)b * DD + gz) * HH + gy) * WW + gx) * 8;
#pragma unroll
    for (int c = 0; c < 8; c++) acc[c] = fmaxf(acc[c], 0.0f);
    *(float4*)&g_s1[out]     = make_float4(acc[0], acc[1], acc[2], acc[3]);
    *(float4*)&g_s1[out + 4] = make_float4(acc[4], acc[5], acc[6], acc[7]);
}

// ---------------------------------------------------------------------------
// Kernel 2: conv3d(8->16) + ReLU -- register-tiled scalar (R4 winner),
// now storing output as fp16 (halves store traffic).
// Block (4,8,8)=256 threads, output tile 16x8x8; each thread: 4-voxel x-strip,
// all 16 output channels (acc[4][16]).
// ---------------------------------------------------------------------------
__global__ __launch_bounds__(256, 1)
void k_conv2(const float* __restrict__ w2,
             const float* __restrict__ b2)
{
    extern __shared__ __align__(16) float dsm[];   // 10*10*18*8 floats (57.6 KB)
    __shared__ __align__(16) float ws[27 * 128];   // [tap][ci][co16], 13.8 KB
    __shared__ float bs[16];

    const int tx4 = threadIdx.x;           // 0..3 (x-strip group)
    const int ty  = threadIdx.y;           // 0..7
    const int tz  = threadIdx.z;           // 0..7
    const int tid = (tz * 8 + ty) * 4 + tx4;
    const int b  = blockIdx.z >> 4;
    const int z0 = (blockIdx.z & 15) << 3;
    const int y0 = blockIdx.y << 3;
    const int x0 = blockIdx.x << 4;        // 16-wide x tile

    for (int i = tid; i < 3456; i += 256) {
        int tap = i >> 7, r = i & 127, ci = r >> 4, co = r & 15;
        ws[i] = w2[(co * 8 + ci) * 27 + tap];
    }
    if (tid < 16) bs[tid] = b2[tid];

    for (int idx = tid; idx < 1800; idx += 256) {
        int lz = idx / 180, r = idx % 180, ly = r / 18, lx = r % 18;
        int gz = z0 - 1 + lz, gy = y0 - 1 + ly, gx = x0 - 1 + lx;
        float4 a = make_float4(0.f, 0.f, 0.f, 0.f), c = a;
        if (gz >= 0 && gz < DD && gy >= 0 && gy < HH && gx >= 0 && gx < WW) {
            size_t base = ((((size_t)b * DD + gz) * HH + gy) * WW + gx) * 8;
            a = *(const float4*)&g_s1[base];
            c = *(const float4*)&g_s1[base + 4];
        }
        *(float4*)&dsm[idx * 8]     = a;
        *(float4*)&dsm[idx * 8 + 4] = c;
    }
    __syncthreads();

    float acc[4][16];
#pragma unroll
    for (int v = 0; v < 4; v++)
#pragma unroll
        for (int co = 0; co < 16; co++) acc[v][co] = bs[co];

    const int xb = tx4 * 4;

    for (int kz = 0; kz < 3; kz++)
        for (int ky = 0; ky < 3; ky++) {
            const float* rb = &dsm[(((tz + kz) * 10 + (ty + ky)) * 18 + xb) * 8];
            float in_r[6][8];
#pragma unroll
            for (int p = 0; p < 6; p++) {
                *(float4*)&in_r[p][0] = *(const float4*)(rb + p * 8);
                *(float4*)&in_r[p][4] = *(const float4*)(rb + p * 8 + 4);
            }
            const float* wrow = &ws[(kz * 3 + ky) * 3 * 128];
#pragma unroll
            for (int kx = 0; kx < 3; kx++) {
                const float* wb = wrow + kx * 128;
#pragma unroll
                for (int ci = 0; ci < 8; ci++) {
                    float4 wa = *(const float4*)&wb[ci * 16];
                    float4 wc = *(const float4*)&wb[ci * 16 + 4];
                    float4 we = *(const float4*)&wb[ci * 16 + 8];
                    float4 wg = *(const float4*)&wb[ci * 16 + 12];
#pragma unroll
                    for (int v = 0; v < 4; v++) {
                        float iv = in_r[kx + v][ci];
                        acc[v][0]  = fmaf(iv, wa.x, acc[v][0]);
                        acc[v][1]  = fmaf(iv, wa.y, acc[v][1]);
                        acc[v][2]  = fmaf(iv, wa.z, acc[v][2]);
                        acc[v][3]  = fmaf(iv, wa.w, acc[v][3]);
                        acc[v][4]  = fmaf(iv, wc.x, acc[v][4]);
                        acc[v][5]  = fmaf(iv, wc.y, acc[v][5]);
                        acc[v][6]  = fmaf(iv, wc.z, acc[v][6]);
                        acc[v][7]  = fmaf(iv, wc.w, acc[v][7]);
                        acc[v][8]  = fmaf(iv, we.x, acc[v][8]);
                        acc[v][9]  = fmaf(iv, we.y, acc[v][9]);
                        acc[v][10] = fmaf(iv, we.z, acc[v][10]);
                        acc[v][11] = fmaf(iv, we.w, acc[v][11]);
                        acc[v][12] = fmaf(iv, wg.x, acc[v][12]);
                        acc[v][13] = fmaf(iv, wg.y, acc[v][13]);
                        acc[v][14] = fmaf(iv, wg.z, acc[v][14]);
                        acc[v][15] = fmaf(iv, wg.w, acc[v][15]);
                    }
                }
            }
        }

    const int gz = z0 + tz, gy = y0 + ty;
#pragma unroll
    for (int v = 0; v < 4; v++) {
        const int gx = x0 + xb + v;
        size_t outb = ((((size_t)b * DD + gz) * HH + gy) * WW + gx) * 16;
        __align__(16) __half2 hp[8];
#pragma unroll
        for (int q = 0; q < 8; q++)
            hp[q] = __floats2half2_rn(fmaxf(acc[v][2 * q], 0.0f),
                                      fmaxf(acc[v][2 * q + 1], 0.0f));
        *(uint4*)&g_s2h[outb]     = *(const uint4*)&hp[0];
        *(uint4*)&g_s2h[outb + 8] = *(const uint4*)&hp[4];
    }
}

// ---------------------------------------------------------------------------
// Kernel 3: conv3d(16->1) + tanh -- fp16 input tile (half the read traffic,
// which was the binding resource). half2 -> float2 conversion in registers.
// Static smem: 1000*16 half = 32 KB tile + weights.
// ---------------------------------------------------------------------------
__global__ __launch_bounds__(512, 2)
void k_conv3(const float* __restrict__ w3,
             const float* __restrict__ b3,
             float* __restrict__ out)
{
    __shared__ __align__(16) __half tileh[1000 * 16];  // 32 KB
    __shared__ __align__(16) float ws[27 * 16];        // [tap][ci]
    __shared__ float bsv;

    const int tx = threadIdx.x, ty = threadIdx.y, tz = threadIdx.z;
    const int tid = (tz * 8 + ty) * 8 + tx;
    const int b  = blockIdx.z >> 4;
    const int z0 = (blockIdx.z & 15) << 3;
    const int y0 = blockIdx.y << 3;
    const int x0 = blockIdx.x << 3;

    if (tid < 432) {
        int tap = tid >> 4, ci = tid & 15;
        ws[tid] = w3[ci * 27 + tap];
    }
    if (tid == 0) bsv = b3[0];

    // stage fp16 tile: 1000 positions x 2 x 16B chunks
    for (int idx = tid; idx < 2000; idx += 512) {
        int pos = idx >> 1, q = idx & 1;
        int lz = pos / 100, rr = pos % 100, ly = rr / 10, lx = rr % 10;
        int gz = z0 - 1 + lz, gy = y0 - 1 + ly, gx = x0 - 1 + lx;
        uint4 v = make_uint4(0u, 0u, 0u, 0u);
        if (gz >= 0 && gz < DD && gy >= 0 && gy < HH && gx >= 0 && gx < WW) {
            size_t base = ((((size_t)b * DD + gz) * HH + gy) * WW + gx) * 16 + q * 8;
            v = *(const uint4*)&g_s2h[base];
        }
        *(uint4*)&tileh[pos * 16 + q * 8] = v;
    }
    __syncthreads();

    float acc = bsv;
#pragma unroll
    for (int kz = 0; kz < 3; kz++)
#pragma unroll
        for (int ky = 0; ky < 3; ky++)
#pragma unroll
            for (int kx = 0; kx < 3; kx++) {
                const int tap = (kz * 3 + ky) * 3 + kx;
                const __half2* ip = (const __half2*)
                    &tileh[(((tz + kz) * 10 + (ty + ky)) * 10 + (tx + kx)) * 16];
                const float* wb = &ws[tap * 16];
#pragma unroll
                for (int k = 0; k < 8; k++) {
                    float2 f = __half22float2(ip[k]);
                    acc = fmaf(f.x, wb[2 * k],     acc);
                    acc = fmaf(f.y, wb[2 * k + 1], acc);
                }
            }

    const int gz = z0 + tz, gy = y0 + ty, gx = x0 + tx;
    out[(((size_t)b * DD + gz) * HH + gy) * WW + gx] = tanhf(acc);
}

// ---------------------------------------------------------------------------
extern "C" void kernel_launch(void* const* d_in, const int* in_sizes, int n_in,
                              void* d_out, int out_size)
{
    const float* x  = (const float*)d_in[0];
    const float* w1 = (const float*)d_in[1];
    const float* b1 = (const float*)d_in[2];
    const float* w2 = (const float*)d_in[3];
    const float* b2 = (const float*)d_in[4];
    const float* w3 = (const float*)d_in[5];
    const float* b3 = (const float*)d_in[6];
    float* out = (float*)d_out;

    static bool attr_set = false;  // idempotent attribute set (not a work guard)
    if (!attr_set) {
        cudaFuncSetAttribute(k_conv2, cudaFuncAttributeMaxDynamicSharedMemorySize,
                             10 * 10 * 18 * 8 * sizeof(float));
        attr_set = true;
    }

    dim3 blk1(8, 8, 8);
    dim3 grd1(WW / 8, HH / 8, (DD / 8) * BB);
    dim3 blk2(4, 8, 8);
    dim3 grd2(WW / 16, HH / 8, (DD / 8) * BB);

    k_conv1<<<grd1, blk1>>>(x, w1, b1);
    k_conv2<<<grd2, blk2, 10 * 10 * 18 * 8 * sizeof(float)>>>(w2, b2);
    k_conv3<<<grd1, blk1>>>(w3, b3, out);
}

// round 9
// speedup vs baseline: 10.8591x; 1.6610x over previous
#include <cuda_runtime.h>
#include <cuda_fp16.h>
#include <math.h>
#include <stdint.h>

// Problem dims
#define BB 2
#define DD 128
#define HH 128
#define WW 128
#define CW 0.1f
#define TWO_PI 6.283185307179586f

// Channels-last scratch buffers (__device__ globals, not cudaMalloc)
__device__ __half g_s1h[(size_t)BB * DD * HH * WW * 8];   // conv1 out fp16
__device__ __half g_s2h[(size_t)BB * DD * HH * WW * 16];  // conv2 out fp16

__device__ __forceinline__ uint32_t smem_u32(const void* p) {
    uint32_t a;
    asm("{ .reg .u64 t; cvta.to.shared.u64 t, %1; cvt.u32.u64 %0, t; }"
        : "=r"(a) : "l"(p));
    return a;
}
__device__ __forceinline__ void ldmatrix_x4(uint32_t& a0, uint32_t& a1,
                                            uint32_t& a2, uint32_t& a3, uint32_t addr) {
    asm volatile("ldmatrix.sync.aligned.m8n8.x4.shared.b16 {%0,%1,%2,%3}, [%4];"
                 : "=r"(a0), "=r"(a1), "=r"(a2), "=r"(a3) : "r"(addr));
}
__device__ __forceinline__ void mma16816(float* d, uint32_t a0, uint32_t a1,
                                         uint32_t a2, uint32_t a3,
                                         uint32_t b0, uint32_t b1) {
    asm volatile(
        "mma.sync.aligned.m16n8k16.row.col.f32.f16.f16.f32 "
        "{%0,%1,%2,%3}, {%4,%5,%6,%7}, {%8,%9}, {%0,%1,%2,%3};"
        : "+f"(d[0]), "+f"(d[1]), "+f"(d[2]), "+f"(d[3])
        : "r"(a0), "r"(a1), "r"(a2), "r"(a3), "r"(b0), "r"(b1));
}

// ---------------------------------------------------------------------------
// Kernel 1: field modulation + conv3d(1->8) + ReLU; fp16 channels-last out
// ---------------------------------------------------------------------------
__global__ __launch_bounds__(512, 2)
void k_conv1(const float* __restrict__ x,
             const float* __restrict__ w1,
             const float* __restrict__ b1)
{
    __shared__ __align__(16) float tile[10 * 10 * 10];
    __shared__ __align__(16) float wk[27 * 8];
    __shared__ float bs[8];

    const int tx = threadIdx.x, ty = threadIdx.y, tz = threadIdx.z;
    const int tid = (tz * 8 + ty) * 8 + tx;
    const int b  = blockIdx.z >> 4;
    const int z0 = (blockIdx.z & 15) << 3;
    const int y0 = blockIdx.y << 3;
    const int x0 = blockIdx.x << 3;

    if (tid < 216) {
        int tap = tid >> 3, co = tid & 7;
        wk[tid] = w1[co * 27 + tap];
    }
    if (tid < 8) bs[tid] = b1[tid];

    const float inv = TWO_PI / (float)(DD + HH + WW);
    for (int idx = tid; idx < 1000; idx += 512) {
        int lz = idx / 100, r = idx % 100, ly = r / 10, lx = r % 10;
        int gz = z0 - 1 + lz, gy = y0 - 1 + ly, gx = x0 - 1 + lx;
        float v = 0.0f;
        if (gz >= 0 && gz < DD && gy >= 0 && gy < HH && gx >= 0 && gx < WW) {
            v = x[(((size_t)b * DD + gz) * HH + gy) * WW + gx];
            float s = (float)(gz + gy + gx);
            v *= 1.0f + CW * sinf(inv * s);
        }
        tile[idx] = v;
    }
    __syncthreads();

    float acc[8];
#pragma unroll
    for (int c = 0; c < 8; c++) acc[c] = bs[c];

#pragma unroll
    for (int kz = 0; kz < 3; kz++)
#pragma unroll
        for (int ky = 0; ky < 3; ky++)
#pragma unroll
            for (int kx = 0; kx < 3; kx++) {
                float v = tile[((tz + kz) * 10 + (ty + ky)) * 10 + (tx + kx)];
                int tap = (kz * 3 + ky) * 3 + kx;
                float4 wa = *(const float4*)&wk[tap * 8];
                float4 wb = *(const float4*)&wk[tap * 8 + 4];
                acc[0] = fmaf(v, wa.x, acc[0]);
                acc[1] = fmaf(v, wa.y, acc[1]);
                acc[2] = fmaf(v, wa.z, acc[2]);
                acc[3] = fmaf(v, wa.w, acc[3]);
                acc[4] = fmaf(v, wb.x, acc[4]);
                acc[5] = fmaf(v, wb.y, acc[5]);
                acc[6] = fmaf(v, wb.z, acc[6]);
                acc[7] = fmaf(v, wb.w, acc[7]);
            }

    const int gz = z0 + tz, gy = y0 + ty, gx = x0 + tx;
    size_t out = ((((size_t)b * DD + gz) * HH + gy) * WW + gx) * 8;
    __align__(16) __half2 hp[4];
#pragma unroll
    for (int q = 0; q < 4; q++)
        hp[q] = __floats2half2_rn(fmaxf(acc[2 * q], 0.0f),
                                  fmaxf(acc[2 * q + 1], 0.0f));
    *(uint4*)&g_s1h[out] = *(const uint4*)&hp[0];
}

// ---------------------------------------------------------------------------
// Kernel 2: conv3d(8->16) + ReLU via mma.sync m16n8k16 (base-PTX tensor path).
// A: channels-last fp16 x-line in smem; ldmatrix.x4 with row m = voxel x0+m
//    (16B), k-block select = +1 voxel. Per (kz,ky): MMA#1 covers kx{0,1},
//    MMA#2 covers kx=2 with k8-15 rows sourced from a zero buffer.
// B: per-lane fragments precomputed in smem (18 tap-matrices x 2 n-halves).
// Block: 256 thr (8 warps), tile 8z x 4y x 128x; warp w owns m-tile w.
// ---------------------------------------------------------------------------
#define C2_ZT 8
#define C2_YT 4
#define C2_LSTRIDE 2176          // 136 voxel slots * 16 B
#define C2_NLINES 60             // 10 z * 6 y input lines

__global__ __launch_bounds__(256, 1)
void k_conv2(const float* __restrict__ w2,
             const float* __restrict__ b2)
{
    extern __shared__ __align__(128) unsigned char dsm[];   // 60*2176 B
    __shared__ __align__(8) uint2 Bsm[18 * 2 * 32];         // 9216 B
    __shared__ float bs[16];
    __shared__ __align__(16) uint4 zbuf;                    // zero A-rows

    const int tid = threadIdx.x;
    const int wid = tid >> 5;
    const int lane = tid & 31;
    const int b  = blockIdx.z;
    const int z0 = blockIdx.y * C2_ZT;
    const int y0 = blockIdx.x * C2_YT;

    const uint32_t dsm_b = smem_u32(dsm);
    const uint32_t zb    = smem_u32(&zbuf);

    if (tid == 0) zbuf = make_uint4(0u, 0u, 0u, 0u);
    if (tid < 16) bs[tid] = b2[tid];

    // B fragments: j = kzky*2+kxp; lane holds b0 = (ci0,ci0+1)@kx_lo,
    // b1 = (ci0,ci0+1)@kx_hi (zero for kxp=1). n = nh*8 + lane/4.
    for (int idx = tid; idx < 18 * 2 * 32; idx += 256) {
        int l    = idx & 31;
        int nh   = (idx >> 5) & 1;
        int j    = idx >> 6;
        int kxp  = j & 1, kzky = j >> 1;
        int kz = kzky / 3, ky = kzky % 3;
        int co = nh * 8 + (l >> 2);
        int ci0 = (l & 3) * 2;
        int kxlo = (kxp == 0) ? 0 : 2;
        int tapb = kz * 9 + ky * 3;
        float w00 = w2[(co * 8 + ci0)     * 27 + tapb + kxlo];
        float w01 = w2[(co * 8 + ci0 + 1) * 27 + tapb + kxlo];
        __half2 h0 = __floats2half2_rn(w00, w01);
        __half2 h1 = __floats2half2_rn(0.0f, 0.0f);
        if (kxp == 0) {
            float w10 = w2[(co * 8 + ci0)     * 27 + tapb + 1];
            float w11 = w2[(co * 8 + ci0 + 1) * 27 + tapb + 1];
            h1 = __floats2half2_rn(w10, w11);
        }
        Bsm[idx] = make_uint2(*(const uint32_t*)&h0, *(const uint32_t*)&h1);
    }

    // Stage input lines (fp16, already channels-last): slot s = input x+1
    for (int idx = tid; idx < C2_NLINES * 136; idx += 256) {
        int l = idx / 136, s = idx % 136;
        int lz = l / 6, ly = l % 6;
        int gz = z0 - 1 + lz, gy = y0 - 1 + ly, gx = s - 1;
        uint4 st = make_uint4(0u, 0u, 0u, 0u);
        if (gz >= 0 && gz < DD && gy >= 0 && gy < HH && gx >= 0 && gx < WW) {
            size_t base = ((((size_t)b * DD + gz) * HH + gy) * WW + gx) * 8;
            st = *(const uint4*)&g_s1h[base];
        }
        *(uint4*)(dsm + l * C2_LSTRIDE + s * 16) = st;
    }
    __syncthreads();

    const int x0 = wid * 16;            // warp's m-tile (16 x positions)
    const int row = lane & 15;          // ldmatrix row within tile
    const int kb  = lane >> 4;          // k-block (0: lanes 0-15, 1: 16-31)

    for (int line = 0; line < C2_ZT * C2_YT; line++) {
        const int oz = line >> 2, oy = line & 3;
        float acc[2][4];
#pragma unroll
        for (int nh = 0; nh < 2; nh++)
#pragma unroll
            for (int i = 0; i < 4; i++) acc[nh][i] = 0.0f;

#pragma unroll
        for (int kzky = 0; kzky < 9; kzky++) {
            const int l = (oz + kzky / 3) * 6 + (oy + kzky % 3);
            const uint32_t la = dsm_b + l * C2_LSTRIDE;
#pragma unroll
            for (int kxp = 0; kxp < 2; kxp++) {
                uint32_t addr;
                if (kxp == 0)
                    addr = la + (uint32_t)(x0 + row + kb) * 16u;
                else
                    addr = kb ? zb : la + (uint32_t)(x0 + row + 2) * 16u;
                uint32_t a0, a1, a2, a3;
                ldmatrix_x4(a0, a1, a2, a3, addr);
                const int j = kzky * 2 + kxp;
#pragma unroll
                for (int nh = 0; nh < 2; nh++) {
                    uint2 bf = Bsm[(j * 2 + nh) * 32 + lane];
                    mma16816(acc[nh], a0, a1, a2, a3, bf.x, bf.y);
                }
            }
        }

        // epilogue: D[gr][c0..c0+1], D[gr+8][...]; x = x0+gr, co = nh*8+c0
        const int gz = z0 + oz, gy = y0 + oy;
        const int gr = lane >> 2, c0 = (lane & 3) * 2;
        const size_t rowb = (((size_t)b * DD + gz) * HH + gy) * WW;
#pragma unroll
        for (int nh = 0; nh < 2; nh++) {
            const int co0 = nh * 8 + c0;
            float v0 = fmaxf(acc[nh][0] + bs[co0],     0.0f);
            float v1 = fmaxf(acc[nh][1] + bs[co0 + 1], 0.0f);
            float v2 = fmaxf(acc[nh][2] + bs[co0],     0.0f);
            float v3 = fmaxf(acc[nh][3] + bs[co0 + 1], 0.0f);
            __half2 h0 = __floats2half2_rn(v0, v1);
            __half2 h1 = __floats2half2_rn(v2, v3);
            *(uint32_t*)&g_s2h[(rowb + x0 + gr)     * 16 + co0] = *(const uint32_t*)&h0;
            *(uint32_t*)&g_s2h[(rowb + x0 + gr + 8) * 16 + co0] = *(const uint32_t*)&h1;
        }
    }
}

// ---------------------------------------------------------------------------
// Kernel 3: conv3d(16->1) + tanh -- fp16 input tile (proven, unchanged)
// ---------------------------------------------------------------------------
__global__ __launch_bounds__(512, 2)
void k_conv3(const float* __restrict__ w3,
             const float* __restrict__ b3,
             float* __restrict__ out)
{
    __shared__ __align__(16) __half tileh[1000 * 16];
    __shared__ __align__(16) float ws[27 * 16];
    __shared__ float bsv;

    const int tx = threadIdx.x, ty = threadIdx.y, tz = threadIdx.z;
    const int tid = (tz * 8 + ty) * 8 + tx;
    const int b  = blockIdx.z >> 4;
    const int z0 = (blockIdx.z & 15) << 3;
    const int y0 = blockIdx.y << 3;
    const int x0 = blockIdx.x << 3;

    if (tid < 432) {
        int tap = tid >> 4, ci = tid & 15;
        ws[tid] = w3[ci * 27 + tap];
    }
    if (tid == 0) bsv = b3[0];

    for (int idx = tid; idx < 2000; idx += 512) {
        int pos = idx >> 1, q = idx & 1;
        int lz = pos / 100, rr = pos % 100, ly = rr / 10, lx = rr % 10;
        int gz = z0 - 1 + lz, gy = y0 - 1 + ly, gx = x0 - 1 + lx;
        uint4 v = make_uint4(0u, 0u, 0u, 0u);
        if (gz >= 0 && gz < DD && gy >= 0 && gy < HH && gx >= 0 && gx < WW) {
            size_t base = ((((size_t)b * DD + gz) * HH + gy) * WW + gx) * 16 + q * 8;
            v = *(const uint4*)&g_s2h[base];
        }
        *(uint4*)&tileh[pos * 16 + q * 8] = v;
    }
    __syncthreads();

    float acc = bsv;
#pragma unroll
    for (int kz = 0; kz < 3; kz++)
#pragma unroll
        for (int ky = 0; ky < 3; ky++)
#pragma unroll
            for (int kx = 0; kx < 3; kx++) {
                const int tap = (kz * 3 + ky) * 3 + kx;
                const __half2* ip = (const __half2*)
                    &tileh[(((tz + kz) * 10 + (ty + ky)) * 10 + (tx + kx)) * 16];
                const float* wb = &ws[tap * 16];
#pragma unroll
                for (int k = 0; k < 8; k++) {
                    float2 f = __half22float2(ip[k]);
                    acc = fmaf(f.x, wb[2 * k],     acc);
                    acc = fmaf(f.y, wb[2 * k + 1], acc);
                }
            }

    const int gz = z0 + tz, gy = y0 + ty, gx = x0 + tx;
    out[(((size_t)b * DD + gz) * HH + gy) * WW + gx] = tanhf(acc);
}

// ---------------------------------------------------------------------------
extern "C" void kernel_launch(void* const* d_in, const int* in_sizes, int n_in,
                              void* d_out, int out_size)
{
    const float* x  = (const float*)d_in[0];
    const float* w1 = (const float*)d_in[1];
    const float* b1 = (const float*)d_in[2];
    const float* w2 = (const float*)d_in[3];
    const float* b2 = (const float*)d_in[4];
    const float* w3 = (const float*)d_in[5];
    const float* b3 = (const float*)d_in[6];
    float* out = (float*)d_out;

    static bool attr_set = false;  // idempotent attribute set (not a work guard)
    if (!attr_set) {
        cudaFuncSetAttribute(k_conv2, cudaFuncAttributeMaxDynamicSharedMemorySize,
                             C2_NLINES * C2_LSTRIDE);
        attr_set = true;
    }

    dim3 blk1(8, 8, 8);
    dim3 grd1(WW / 8, HH / 8, (DD / 8) * BB);
    dim3 blk2(256, 1, 1);
    dim3 grd2(HH / C2_YT, DD / C2_ZT, BB);

    k_conv1<<<grd1, blk1>>>(x, w1, b1);
    k_conv2<<<grd2, blk2, C2_NLINES * C2_LSTRIDE>>>(w2, b2);
    k_conv3<<<grd1, blk1>>>(w3, b3, out);
}

// round 10
// speedup vs baseline: 12.0852x; 1.1129x over previous
#include <cuda_runtime.h>
#include <cuda_fp16.h>
#include <math.h>
#include <stdint.h>

// Problem dims
#define BB 2
#define DD 128
#define HH 128
#define WW 128
#define CW 0.1f
#define TWO_PI 6.283185307179586f

// Channels-last scratch buffers (__device__ globals, not cudaMalloc)
__device__ __half g_s1h[(size_t)BB * DD * HH * WW * 8];   // conv1 out fp16
__device__ __half g_s2h[(size_t)BB * DD * HH * WW * 16];  // conv2 out fp16

__device__ __forceinline__ uint32_t smem_u32(const void* p) {
    uint32_t a;
    asm("{ .reg .u64 t; cvta.to.shared.u64 t, %1; cvt.u32.u64 %0, t; }"
        : "=r"(a) : "l"(p));
    return a;
}
__device__ __forceinline__ void ldmatrix_x4(uint32_t& a0, uint32_t& a1,
                                            uint32_t& a2, uint32_t& a3, uint32_t addr) {
    asm volatile("ldmatrix.sync.aligned.m8n8.x4.shared.b16 {%0,%1,%2,%3}, [%4];"
                 : "=r"(a0), "=r"(a1), "=r"(a2), "=r"(a3) : "r"(addr));
}
__device__ __forceinline__ void mma16816(float* d, uint32_t a0, uint32_t a1,
                                         uint32_t a2, uint32_t a3,
                                         uint32_t b0, uint32_t b1) {
    asm volatile(
        "mma.sync.aligned.m16n8k16.row.col.f32.f16.f16.f32 "
        "{%0,%1,%2,%3}, {%4,%5,%6,%7}, {%8,%9}, {%0,%1,%2,%3};"
        : "+f"(d[0]), "+f"(d[1]), "+f"(d[2]), "+f"(d[3])
        : "r"(a0), "r"(a1), "r"(a2), "r"(a3), "r"(b0), "r"(b1));
}

// ---------------------------------------------------------------------------
// Kernel 1: field modulation + conv3d(1->8) + ReLU; fp16 channels-last out
// (proven, unchanged)
// ---------------------------------------------------------------------------
__global__ __launch_bounds__(512, 2)
void k_conv1(const float* __restrict__ x,
             const float* __restrict__ w1,
             const float* __restrict__ b1)
{
    __shared__ __align__(16) float tile[10 * 10 * 10];
    __shared__ __align__(16) float wk[27 * 8];
    __shared__ float bs[8];

    const int tx = threadIdx.x, ty = threadIdx.y, tz = threadIdx.z;
    const int tid = (tz * 8 + ty) * 8 + tx;
    const int b  = blockIdx.z >> 4;
    const int z0 = (blockIdx.z & 15) << 3;
    const int y0 = blockIdx.y << 3;
    const int x0 = blockIdx.x << 3;

    if (tid < 216) {
        int tap = tid >> 3, co = tid & 7;
        wk[tid] = w1[co * 27 + tap];
    }
    if (tid < 8) bs[tid] = b1[tid];

    const float inv = TWO_PI / (float)(DD + HH + WW);
    for (int idx = tid; idx < 1000; idx += 512) {
        int lz = idx / 100, r = idx % 100, ly = r / 10, lx = r % 10;
        int gz = z0 - 1 + lz, gy = y0 - 1 + ly, gx = x0 - 1 + lx;
        float v = 0.0f;
        if (gz >= 0 && gz < DD && gy >= 0 && gy < HH && gx >= 0 && gx < WW) {
            v = x[(((size_t)b * DD + gz) * HH + gy) * WW + gx];
            float s = (float)(gz + gy + gx);
            v *= 1.0f + CW * sinf(inv * s);
        }
        tile[idx] = v;
    }
    __syncthreads();

    float acc[8];
#pragma unroll
    for (int c = 0; c < 8; c++) acc[c] = bs[c];

#pragma unroll
    for (int kz = 0; kz < 3; kz++)
#pragma unroll
        for (int ky = 0; ky < 3; ky++)
#pragma unroll
            for (int kx = 0; kx < 3; kx++) {
                float v = tile[((tz + kz) * 10 + (ty + ky)) * 10 + (tx + kx)];
                int tap = (kz * 3 + ky) * 3 + kx;
                float4 wa = *(const float4*)&wk[tap * 8];
                float4 wb = *(const float4*)&wk[tap * 8 + 4];
                acc[0] = fmaf(v, wa.x, acc[0]);
                acc[1] = fmaf(v, wa.y, acc[1]);
                acc[2] = fmaf(v, wa.z, acc[2]);
                acc[3] = fmaf(v, wa.w, acc[3]);
                acc[4] = fmaf(v, wb.x, acc[4]);
                acc[5] = fmaf(v, wb.y, acc[5]);
                acc[6] = fmaf(v, wb.z, acc[6]);
                acc[7] = fmaf(v, wb.w, acc[7]);
            }

    const int gz = z0 + tz, gy = y0 + ty, gx = x0 + tx;
    size_t out = ((((size_t)b * DD + gz) * HH + gy) * WW + gx) * 8;
    __align__(16) __half2 hp[4];
#pragma unroll
    for (int q = 0; q < 4; q++)
        hp[q] = __floats2half2_rn(fmaxf(acc[2 * q], 0.0f),
                                  fmaxf(acc[2 * q + 1], 0.0f));
    *(uint4*)&g_s1h[out] = *(const uint4*)&hp[0];
}

// ---------------------------------------------------------------------------
// Kernel 2: conv3d(8->16) + ReLU via mma.sync m16n8k16.
// Changes vs R8 winner: 512 thr / 16 warps (4 per SMSP), 8z x 8y tile
// (halo 1.56x, 100 lines = 217.6 KB dynamic smem), B-fragments held in
// 36 uint2 REGISTERS per lane (loaded once from gmem; zero mainloop B-LDS),
// warps sweep independent (line, m-tile) tasks with no syncs.
// ---------------------------------------------------------------------------
#define C2_ZT 8
#define C2_YT 8
#define C2_LSTRIDE 2176          // 136 voxel slots * 16 B
#define C2_NLINES 100            // 10 z * 10 y input lines

__global__ __launch_bounds__(512, 1)
void k_conv2(const float* __restrict__ w2,
             const float* __restrict__ b2)
{
    extern __shared__ __align__(128) unsigned char dsm[];   // 100*2176 = 217600 B
    __shared__ float bs[16];
    __shared__ __align__(16) uint4 zbuf;                    // zero A-rows

    const int tid = threadIdx.x;
    const int wid = tid >> 5;
    const int lane = tid & 31;
    const int b  = blockIdx.z;
    const int z0 = blockIdx.y * C2_ZT;
    const int y0 = blockIdx.x * C2_YT;

    const uint32_t dsm_b = smem_u32(dsm);
    const uint32_t zb    = smem_u32(&zbuf);

    if (tid == 0) zbuf = make_uint4(0u, 0u, 0u, 0u);
    if (tid < 16) bs[tid] = b2[tid];

    // B fragments in registers: Bf[j*2+nh], j=kzky*2+kxp.
    // lane: co = nh*8 + lane/4, ci0 = (lane&3)*2 (same verified mapping as R8).
    uint2 Bf[36];
    {
        const int lco = lane >> 2, ci0 = (lane & 3) * 2;
#pragma unroll
        for (int j = 0; j < 18; j++) {
            const int kxp = j & 1, kzky = j >> 1;
            const int kz = kzky / 3, ky = kzky % 3;
            const int tapb = kz * 9 + ky * 3;
            const int kxlo = (kxp == 0) ? 0 : 2;
#pragma unroll
            for (int nh = 0; nh < 2; nh++) {
                const int co = nh * 8 + lco;
                float w00 = w2[(co * 8 + ci0)     * 27 + tapb + kxlo];
                float w01 = w2[(co * 8 + ci0 + 1) * 27 + tapb + kxlo];
                __half2 h0 = __floats2half2_rn(w00, w01);
                __half2 h1 = __floats2half2_rn(0.0f, 0.0f);
                if (kxp == 0) {
                    float w10 = w2[(co * 8 + ci0)     * 27 + tapb + 1];
                    float w11 = w2[(co * 8 + ci0 + 1) * 27 + tapb + 1];
                    h1 = __floats2half2_rn(w10, w11);
                }
                Bf[j * 2 + nh] = make_uint2(*(const uint32_t*)&h0,
                                            *(const uint32_t*)&h1);
            }
        }
    }

    // Stage input lines (fp16 channels-last): slot s = input x+1
    for (int idx = tid; idx < C2_NLINES * 136; idx += 512) {
        int l = idx / 136, s = idx % 136;
        int lz = l / 10, ly = l % 10;
        int gz = z0 - 1 + lz, gy = y0 - 1 + ly, gx = s - 1;
        uint4 st = make_uint4(0u, 0u, 0u, 0u);
        if (gz >= 0 && gz < DD && gy >= 0 && gy < HH && gx >= 0 && gx < WW) {
            size_t base = ((((size_t)b * DD + gz) * HH + gy) * WW + gx) * 8;
            st = *(const uint4*)&g_s1h[base];
        }
        *(uint4*)(dsm + l * C2_LSTRIDE + s * 16) = st;
    }
    __syncthreads();

    const int row = lane & 15;          // ldmatrix row within m-tile
    const int kb  = lane >> 4;          // k-block (0: lanes 0-15, 1: 16-31)
    const int gr = lane >> 2, c0 = (lane & 3) * 2;

    // 512 tasks: task = oline*8 + mtile; oline = oz*8+oy (64 lines)
    for (int t = wid; t < C2_ZT * C2_YT * 8; t += 16) {
        const int mtile = t & 7;
        const int oline = t >> 3;
        const int oz = oline >> 3, oy = oline & 7;
        const int x0 = mtile * 16;

        float acc[2][4];
#pragma unroll
        for (int nh = 0; nh < 2; nh++)
#pragma unroll
            for (int i = 0; i < 4; i++) acc[nh][i] = 0.0f;

#pragma unroll
        for (int kzky = 0; kzky < 9; kzky++) {
            const int l = (oz + kzky / 3) * 10 + (oy + kzky % 3);
            const uint32_t la = dsm_b + l * C2_LSTRIDE;
#pragma unroll
            for (int kxp = 0; kxp < 2; kxp++) {
                uint32_t addr;
                if (kxp == 0)
                    addr = la + (uint32_t)(x0 + row + kb) * 16u;
                else
                    addr = kb ? zb : la + (uint32_t)(x0 + row + 2) * 16u;
                uint32_t a0, a1, a2, a3;
                ldmatrix_x4(a0, a1, a2, a3, addr);
                const int j = kzky * 2 + kxp;
#pragma unroll
                for (int nh = 0; nh < 2; nh++)
                    mma16816(acc[nh], a0, a1, a2, a3,
                             Bf[j * 2 + nh].x, Bf[j * 2 + nh].y);
            }
        }

        const int gz = z0 + oz, gy = y0 + oy;
        const size_t rowb = (((size_t)b * DD + gz) * HH + gy) * WW;
#pragma unroll
        for (int nh = 0; nh < 2; nh++) {
            const int co0 = nh * 8 + c0;
            float v0 = fmaxf(acc[nh][0] + bs[co0],     0.0f);
            float v1 = fmaxf(acc[nh][1] + bs[co0 + 1], 0.0f);
            float v2 = fmaxf(acc[nh][2] + bs[co0],     0.0f);
            float v3 = fmaxf(acc[nh][3] + bs[co0 + 1], 0.0f);
            __half2 h0 = __floats2half2_rn(v0, v1);
            __half2 h1 = __floats2half2_rn(v2, v3);
            *(uint32_t*)&g_s2h[(rowb + x0 + gr)     * 16 + co0] = *(const uint32_t*)&h0;
            *(uint32_t*)&g_s2h[(rowb + x0 + gr + 8) * 16 + co0] = *(const uint32_t*)&h1;
        }
    }
}

// ---------------------------------------------------------------------------
// Kernel 3: conv3d(16->1) + tanh -- 2-voxel x-strip per thread; per (kz,ky)
// the 4-position fp16 window converts once into fin[4][16] registers and is
// reused across (kx, voxel) -> fewer LDS wavefronts + cvts than 1-voxel form.
// ---------------------------------------------------------------------------
__global__ __launch_bounds__(256, 2)
void k_conv3(const float* __restrict__ w3,
             const float* __restrict__ b3,
             float* __restrict__ out)
{
    __shared__ __align__(16) __half tileh[1000 * 16];   // 32 KB
    __shared__ __align__(16) float ws[27 * 16];
    __shared__ float bsv;

    const int tx = threadIdx.x;          // 0..3, strip of 2 x-voxels
    const int ty = threadIdx.y, tz = threadIdx.z;
    const int tid = (tz * 8 + ty) * 4 + tx;
    const int b  = blockIdx.z >> 4;
    const int z0 = (blockIdx.z & 15) << 3;
    const int y0 = blockIdx.y << 3;
    const int x0 = blockIdx.x << 3;

    if (tid < 216) {                     // 2 per thread covers 432
        ws[tid]       = w3[(tid & 15) * 27 + (tid >> 4)];
        int t2 = tid + 216;
        ws[t2]        = w3[(t2 & 15) * 27 + (t2 >> 4)];
    }
    if (tid == 0) bsv = b3[0];

    for (int idx = tid; idx < 2000; idx += 256) {
        int pos = idx >> 1, q = idx & 1;
        int lz = pos / 100, rr = pos % 100, ly = rr / 10, lx = rr % 10;
        int gz = z0 - 1 + lz, gy = y0 - 1 + ly, gx = x0 - 1 + lx;
        uint4 v = make_uint4(0u, 0u, 0u, 0u);
        if (gz >= 0 && gz < DD && gy >= 0 && gy < HH && gx >= 0 && gx < WW) {
            size_t base = ((((size_t)b * DD + gz) * HH + gy) * WW + gx) * 16 + q * 8;
            v = *(const uint4*)&g_s2h[base];
        }
        *(uint4*)&tileh[pos * 16 + q * 8] = v;
    }
    __syncthreads();

    float acc0 = bsv, acc1 = 0.0f;

#pragma unroll
    for (int kz = 0; kz < 3; kz++)
#pragma unroll
        for (int ky = 0; ky < 3; ky++) {
            const int base = ((tz + kz) * 10 + (ty + ky)) * 10 + tx * 2;
            float fin[4][16];
#pragma unroll
            for (int p = 0; p < 4; p++) {
                const __half2* ip = (const __half2*)&tileh[(base + p) * 16];
#pragma unroll
                for (int k = 0; k < 8; k++) {
                    float2 f = __half22float2(ip[k]);
                    fin[p][2 * k]     = f.x;
                    fin[p][2 * k + 1] = f.y;
                }
            }
#pragma unroll
            for (int kx = 0; kx < 3; kx++) {
                const float* wb = &ws[((kz * 3 + ky) * 3 + kx) * 16];
#pragma unroll
                for (int q = 0; q < 4; q++) {
                    float4 wv = *(const float4*)&wb[q * 4];
                    acc0 = fmaf(fin[kx][q * 4 + 0],     wv.x, acc0);
                    acc0 = fmaf(fin[kx][q * 4 + 1],     wv.y, acc0);
                    acc0 = fmaf(fin[kx][q * 4 + 2],     wv.z, acc0);
                    acc0 = fmaf(fin[kx][q * 4 + 3],     wv.w, acc0);
                    acc1 = fmaf(fin[kx + 1][q * 4 + 0], wv.x, acc1);
                    acc1 = fmaf(fin[kx + 1][q * 4 + 1], wv.y, acc1);
                    acc1 = fmaf(fin[kx + 1][q * 4 + 2], wv.z, acc1);
                    acc1 = fmaf(fin[kx + 1][q * 4 + 3], wv.w, acc1);
                }
            }
        }

    const int gz = z0 + tz, gy = y0 + ty, gx = x0 + tx * 2;
    size_t ob = (((size_t)b * DD + gz) * HH + gy) * WW + gx;
    out[ob]     = tanhf(acc0);
    out[ob + 1] = tanhf(acc1 + bsv);
}

// ---------------------------------------------------------------------------
extern "C" void kernel_launch(void* const* d_in, const int* in_sizes, int n_in,
                              void* d_out, int out_size)
{
    const float* x  = (const float*)d_in[0];
    const float* w1 = (const float*)d_in[1];
    const float* b1 = (const float*)d_in[2];
    const float* w2 = (const float*)d_in[3];
    const float* b2 = (const float*)d_in[4];
    const float* w3 = (const float*)d_in[5];
    const float* b3 = (const float*)d_in[6];
    float* out = (float*)d_out;

    static bool attr_set = false;  // idempotent attribute set (not a work guard)
    if (!attr_set) {
        cudaFuncSetAttribute(k_conv2, cudaFuncAttributeMaxDynamicSharedMemorySize,
                             C2_NLINES * C2_LSTRIDE);
        attr_set = true;
    }

    dim3 blk1(8, 8, 8);
    dim3 grd1(WW / 8, HH / 8, (DD / 8) * BB);
    dim3 blk2(512, 1, 1);
    dim3 grd2(HH / C2_YT, DD / C2_ZT, BB);
    dim3 blk3(4, 8, 8);

    k_conv1<<<grd1, blk1>>>(x, w1, b1);
    k_conv2<<<grd2, blk2, C2_NLINES * C2_LSTRIDE>>>(w2, b2);
    k_conv3<<<grd1, blk3>>>(w3, b3, out);
}